// round 1
// baseline (speedup 1.0000x reference)
#include <cuda_runtime.h>
#include <cstdint>

#define BB 2
#define SS 2048
#define EE 768
#define HH 12
#define DD 64
#define FFF 3072
#define MM (BB*SS)          // 4096 rows

// ---------------- scratch (device globals; no allocation) ----------------
__device__ float g_q  [MM*EE];
__device__ float g_k  [MM*EE];
__device__ float g_v  [MM*EE];
__device__ float g_ctx[MM*EE];
__device__ float g_h  [MM*EE];
__device__ float g_ff1[(size_t)MM*FFF];

// ---------------- generic SGEMM: C = A[MxK] @ B[KxN] + bias, opt ReLU ----
// 128x128 block tile, BK=16, 256 threads, 8x8 per-thread microtile.
template<bool RELU>
__global__ __launch_bounds__(256) void sgemm_kernel(
    const float* __restrict__ A, const float* __restrict__ B,
    const float* __restrict__ bias, float* __restrict__ C,
    int M, int N, int K)
{
    __shared__ float As[16][132];   // transposed A tile [k][m], padded
    __shared__ float Bs[16][128];   // B tile [k][n]

    const int t  = threadIdx.x;
    const int m0 = blockIdx.y * 128;
    const int n0 = blockIdx.x * 128;
    const int tx = t & 15;          // 16 col groups of 8
    const int ty = t >> 4;          // 16 row groups of 8

    float acc[8][8];
#pragma unroll
    for (int i = 0; i < 8; i++)
#pragma unroll
        for (int j = 0; j < 8; j++) acc[i][j] = 0.f;

    for (int kt = 0; kt < K; kt += 16) {
#pragma unroll
        for (int i = 0; i < 2; i++) {
            int idx = t + i * 256;                 // 0..511 (512 float4s each)
            int row = idx >> 2, c4 = idx & 3;      // A: 128 rows x 4 float4
            float4 av = *(const float4*)&A[(size_t)(m0 + row) * K + kt + c4 * 4];
            As[c4 * 4 + 0][row] = av.x;
            As[c4 * 4 + 1][row] = av.y;
            As[c4 * 4 + 2][row] = av.z;
            As[c4 * 4 + 3][row] = av.w;
            int kr = idx >> 5, n4 = idx & 31;      // B: 16 rows x 32 float4
            *(float4*)&Bs[kr][n4 * 4] =
                *(const float4*)&B[(size_t)(kt + kr) * N + n0 + n4 * 4];
        }
        __syncthreads();

#pragma unroll
        for (int kk = 0; kk < 16; kk++) {
            float4 a0 = *(float4*)&As[kk][ty * 8];
            float4 a1 = *(float4*)&As[kk][ty * 8 + 4];
            float4 b0 = *(float4*)&Bs[kk][tx * 8];
            float4 b1 = *(float4*)&Bs[kk][tx * 8 + 4];
            float a[8] = {a0.x, a0.y, a0.z, a0.w, a1.x, a1.y, a1.z, a1.w};
            float b[8] = {b0.x, b0.y, b0.z, b0.w, b1.x, b1.y, b1.z, b1.w};
#pragma unroll
            for (int i = 0; i < 8; i++)
#pragma unroll
                for (int j = 0; j < 8; j++)
                    acc[i][j] = fmaf(a[i], b[j], acc[i][j]);
        }
        __syncthreads();
    }

#pragma unroll
    for (int i = 0; i < 8; i++) {
        int r = m0 + ty * 8 + i;
#pragma unroll
        for (int j4 = 0; j4 < 2; j4++) {
            int c = n0 + tx * 8 + j4 * 4;
            float4 bv = *(const float4*)&bias[c];
            float4 o;
            o.x = acc[i][j4 * 4 + 0] + bv.x;
            o.y = acc[i][j4 * 4 + 1] + bv.y;
            o.z = acc[i][j4 * 4 + 2] + bv.z;
            o.w = acc[i][j4 * 4 + 3] + bv.w;
            if (RELU) {
                o.x = fmaxf(o.x, 0.f); o.y = fmaxf(o.y, 0.f);
                o.z = fmaxf(o.z, 0.f); o.w = fmaxf(o.w, 0.f);
            }
            *(float4*)&C[(size_t)r * N + c] = o;
        }
    }
}

// ---------------- attention scores: P = Q K^T / 8 - |i-j| (pre-softmax) ---
// grid (S/64, S/64, B*H), 256 threads, 64x64 output tile, D=64 in one shot.
__global__ __launch_bounds__(256) void scores_kernel(
    const float* __restrict__ q, const float* __restrict__ k,
    float* __restrict__ P)
{
    __shared__ float Qs[64][64];   // [d][row]
    __shared__ float Ks[64][64];   // [d][row]

    const int bh = blockIdx.z;
    const int b  = bh / HH, h = bh % HH;
    const int q0 = blockIdx.y * 64, k0 = blockIdx.x * 64;
    const int t  = threadIdx.x;

#pragma unroll
    for (int i = 0; i < 4; i++) {
        int idx = t + i * 256;             // 0..1023 float4s
        int row = idx >> 4, c4 = idx & 15;
        size_t qoff = ((size_t)(b * SS + q0 + row) * HH + h) * DD + c4 * 4;
        float4 qv = *(const float4*)&q[qoff];
        Qs[c4 * 4 + 0][row] = qv.x; Qs[c4 * 4 + 1][row] = qv.y;
        Qs[c4 * 4 + 2][row] = qv.z; Qs[c4 * 4 + 3][row] = qv.w;
        size_t koff = ((size_t)(b * SS + k0 + row) * HH + h) * DD + c4 * 4;
        float4 kv = *(const float4*)&k[koff];
        Ks[c4 * 4 + 0][row] = kv.x; Ks[c4 * 4 + 1][row] = kv.y;
        Ks[c4 * 4 + 2][row] = kv.z; Ks[c4 * 4 + 3][row] = kv.w;
    }
    __syncthreads();

    const int tx = t & 15, ty = t >> 4;
    float acc[4][4];
#pragma unroll
    for (int i = 0; i < 4; i++)
#pragma unroll
        for (int j = 0; j < 4; j++) acc[i][j] = 0.f;

#pragma unroll
    for (int kk = 0; kk < 64; kk++) {
        float4 a = *(float4*)&Qs[kk][ty * 4];
        float4 c = *(float4*)&Ks[kk][tx * 4];
        float av[4] = {a.x, a.y, a.z, a.w};
        float cv[4] = {c.x, c.y, c.z, c.w};
#pragma unroll
        for (int i = 0; i < 4; i++)
#pragma unroll
            for (int j = 0; j < 4; j++)
                acc[i][j] = fmaf(av[i], cv[j], acc[i][j]);
    }

    const int kj = k0 + tx * 4;
#pragma unroll
    for (int i = 0; i < 4; i++) {
        int qi = q0 + ty * 4 + i;
        float4 o;
        o.x = acc[i][0] * 0.125f - fabsf((float)(qi - (kj + 0)));
        o.y = acc[i][1] * 0.125f - fabsf((float)(qi - (kj + 1)));
        o.z = acc[i][2] * 0.125f - fabsf((float)(qi - (kj + 2)));
        o.w = acc[i][3] * 0.125f - fabsf((float)(qi - (kj + 3)));
        *(float4*)&P[((size_t)bh * SS + qi) * SS + kj] = o;
    }
}

// ---------------- row softmax over 2048 cols, in place --------------------
__global__ __launch_bounds__(256) void softmax_kernel(float* __restrict__ P)
{
    __shared__ float red[256];
    float* p = P + (size_t)blockIdx.x * SS;
    const int t = threadIdx.x;

    float v[8];
    float m = -1e30f;
#pragma unroll
    for (int i = 0; i < 8; i++) { v[i] = p[t + i * 256]; m = fmaxf(m, v[i]); }
    red[t] = m; __syncthreads();
    for (int s = 128; s > 0; s >>= 1) {
        if (t < s) red[t] = fmaxf(red[t], red[t + s]);
        __syncthreads();
    }
    m = red[0]; __syncthreads();

    float sum = 0.f;
#pragma unroll
    for (int i = 0; i < 8; i++) { v[i] = __expf(v[i] - m); sum += v[i]; }
    red[t] = sum; __syncthreads();
    for (int s = 128; s > 0; s >>= 1) {
        if (t < s) red[t] += red[t + s];
        __syncthreads();
    }
    const float inv = 1.0f / red[0];
#pragma unroll
    for (int i = 0; i < 8; i++) p[t + i * 256] = v[i] * inv;
}

// ---------------- ctx = P @ V : per (b,h) [2048,2048]@[2048,64] -----------
// grid (S/128, B*H), 256 threads, 128x64 tile, BK=32, 8x4 microtile.
__global__ __launch_bounds__(256) void ctx_kernel(
    const float* __restrict__ P, const float* __restrict__ v,
    float* __restrict__ ctx)
{
    __shared__ float Ps[128][33];
    __shared__ float Vs[32][64];

    const int bh = blockIdx.y;
    const int b  = bh / HH, h = bh % HH;
    const int q0 = blockIdx.x * 128;
    const int t  = threadIdx.x;
    const int tx = t & 15, ty = t >> 4;
    const float* Pb = P + (size_t)bh * SS * SS;

    float acc[8][4];
#pragma unroll
    for (int i = 0; i < 8; i++)
#pragma unroll
        for (int j = 0; j < 4; j++) acc[i][j] = 0.f;

    for (int kt = 0; kt < SS; kt += 32) {
#pragma unroll
        for (int i = 0; i < 4; i++) {
            int idx = t + i * 256;               // 1024 float4s = 128x32
            int row = idx >> 3, c4 = idx & 7;
            float4 pv = *(const float4*)&Pb[(size_t)(q0 + row) * SS + kt + c4 * 4];
            Ps[row][c4 * 4 + 0] = pv.x; Ps[row][c4 * 4 + 1] = pv.y;
            Ps[row][c4 * 4 + 2] = pv.z; Ps[row][c4 * 4 + 3] = pv.w;
        }
#pragma unroll
        for (int i = 0; i < 2; i++) {
            int idx = t + i * 256;               // 512 float4s = 32x64
            int kr = idx >> 4, c4 = idx & 15;
            *(float4*)&Vs[kr][c4 * 4] =
                *(const float4*)&v[((size_t)(b * SS + kt + kr) * HH + h) * DD + c4 * 4];
        }
        __syncthreads();

#pragma unroll
        for (int kk = 0; kk < 32; kk++) {
            float4 bv = *(float4*)&Vs[kk][tx * 4];
#pragma unroll
            for (int i = 0; i < 8; i++) {
                float a = Ps[ty * 8 + i][kk];
                acc[i][0] = fmaf(a, bv.x, acc[i][0]);
                acc[i][1] = fmaf(a, bv.y, acc[i][1]);
                acc[i][2] = fmaf(a, bv.z, acc[i][2]);
                acc[i][3] = fmaf(a, bv.w, acc[i][3]);
            }
        }
        __syncthreads();
    }

#pragma unroll
    for (int i = 0; i < 8; i++) {
        float4 o = {acc[i][0], acc[i][1], acc[i][2], acc[i][3]};
        *(float4*)&ctx[((size_t)(b * SS + q0 + ty * 8 + i) * HH + h) * DD + tx * 4] = o;
    }
}

// ---------------- out = LayerNorm(A + B) * g + be --------------------------
__global__ __launch_bounds__(256) void add_ln_kernel(
    const float* __restrict__ A, const float* __restrict__ Bi,
    const float* __restrict__ g, const float* __restrict__ be,
    float* __restrict__ out)
{
    __shared__ float rs[256];
    __shared__ float rs2[256];
    const size_t off = (size_t)blockIdx.x * EE;
    const int t = threadIdx.x;

    float x[3];
    float s = 0.f, s2 = 0.f;
#pragma unroll
    for (int i = 0; i < 3; i++) {
        int c = t + i * 256;
        x[i] = A[off + c] + Bi[off + c];
        s += x[i]; s2 += x[i] * x[i];
    }
    rs[t] = s; rs2[t] = s2; __syncthreads();
    for (int st = 128; st > 0; st >>= 1) {
        if (t < st) { rs[t] += rs[t + st]; rs2[t] += rs2[t + st]; }
        __syncthreads();
    }
    const float mu  = rs[0] * (1.0f / EE);
    const float var = rs2[0] * (1.0f / EE) - mu * mu;
    const float r   = rsqrtf(var + 1e-5f);
#pragma unroll
    for (int i = 0; i < 3; i++) {
        int c = t + i * 256;
        out[off + c] = (x[i] - mu) * r * g[c] + be[c];
    }
}

// ---------------- launch --------------------------------------------------
extern "C" void kernel_launch(void* const* d_in, const int* in_sizes, int n_in,
                              void* d_out, int out_size)
{
    const float* x  = (const float*)d_in[0];
    const float* Wq = (const float*)d_in[1];
    const float* bq = (const float*)d_in[2];
    const float* Wk = (const float*)d_in[3];
    const float* bk = (const float*)d_in[4];
    const float* Wv = (const float*)d_in[5];
    const float* bv = (const float*)d_in[6];
    const float* Wo = (const float*)d_in[7];
    const float* bo = (const float*)d_in[8];
    const float* W1 = (const float*)d_in[9];
    const float* b1 = (const float*)d_in[10];
    const float* W2 = (const float*)d_in[11];
    const float* b2 = (const float*)d_in[12];
    const float* g1 = (const float*)d_in[13];
    const float* be1= (const float*)d_in[14];
    const float* g2 = (const float*)d_in[15];
    const float* be2= (const float*)d_in[16];

    float* out  = (float*)d_out;
    float* attn = out + (size_t)BB * SS * EE;   // [B,H,S,S] region of d_out

    float *q, *k, *v, *ctxp, *h, *ff1;
    cudaGetSymbolAddress((void**)&q,    g_q);
    cudaGetSymbolAddress((void**)&k,    g_k);
    cudaGetSymbolAddress((void**)&v,    g_v);
    cudaGetSymbolAddress((void**)&ctxp, g_ctx);
    cudaGetSymbolAddress((void**)&h,    g_h);
    cudaGetSymbolAddress((void**)&ff1,  g_ff1);

    dim3 gE (EE  / 128, MM / 128);   // (6, 32)
    dim3 gFF(FFF / 128, MM / 128);   // (24, 32)

    // QKV projections
    sgemm_kernel<false><<<gE, 256>>>(x, Wq, bq, q, MM, EE, EE);
    sgemm_kernel<false><<<gE, 256>>>(x, Wk, bk, k, MM, EE, EE);
    sgemm_kernel<false><<<gE, 256>>>(x, Wv, bv, v, MM, EE, EE);

    // attention
    scores_kernel <<<dim3(SS / 64, SS / 64, BB * HH), 256>>>(q, k, attn);
    softmax_kernel<<<BB * HH * SS, 256>>>(attn);
    ctx_kernel    <<<dim3(SS / 128, BB * HH), 256>>>(attn, v, ctxp);

    // output projection (reuse q as attn_out) + residual LN
    sgemm_kernel<false><<<gE, 256>>>(ctxp, Wo, bo, q, MM, EE, EE);
    add_ln_kernel<<<MM, 256>>>(x, q, g1, be1, h);

    // FFN (reuse k as ff2) + residual LN -> final out
    sgemm_kernel<true ><<<gFF, 256>>>(h, W1, b1, ff1, MM, FFF, EE);
    sgemm_kernel<false><<<gE, 256>>>(ff1, W2, b2, k, MM, EE, FFF);
    add_ln_kernel<<<MM, 256>>>(h, k, g2, be2, out);
}